// round 7
// baseline (speedup 1.0000x reference)
#include <cuda_runtime.h>
#include <cstdint>

// Block bk (0..1023): ipair = bk>>3 (row-pair of the 256x32 idx matrix),
// jg = bk&7 (column group of 4). Row slot r=(dm<<2)|dn -> entry
//   m = 2*ipair + dm, n = 4*jg + dn -> flat row = m*32 + n.
// Thread tid owns abs-code A = tid: its table row lives in REGISTERS; the
// block's 8 x-vectors are broadcast from smem. All 4 idx entries of each
// packed word live inside one block -> local pack.

__global__ void __launch_bounds__(256, 5) e8p_fused_kernel(
    const float* __restrict__ X,
    const float* __restrict__ grid,
    const float* __restrict__ grid_norm,
    float* __restrict__ out)
{
    __shared__ __align__(16) float s_x[8][8];
    __shared__ __align__(16) float s_x25[8][8];
    __shared__ float s_p1c[8];
    __shared__ unsigned long long s_key[8];
    __shared__ int s_bestc[8];

    const int tid = threadIdx.x;
    const int ipair = blockIdx.x >> 3;                // 0..127
    const int jg    = blockIdx.x & 7;                 // 0..7

    // ---- Per-thread register table: a[] = grid[A<<8], na = grid_norm[A<<8].
    const int A = tid;
    float a[8], na;
    {
        const float4* g4 = reinterpret_cast<const float4*>(grid + ((size_t)A << 11));
        float4 a0 = g4[0], a1 = g4[1];
        a[0]=a0.x; a[1]=a0.y; a[2]=a0.z; a[3]=a0.w;
        a[4]=a1.x; a[5]=a1.y; a[6]=a1.z; a[7]=a1.w;
        na = grid_norm[A << 8];
    }

    // ---- Stage the block's 8 x-vectors (+x25, p1c) and init keys.
    if (tid < 8) {
        const int r = tid, dm = r >> 2, dn = r & 3;
        const int row = (2 * ipair + dm) * 32 + 4 * jg + dn;
        const float4* xr4 = reinterpret_cast<const float4*>(X + (size_t)row * 8);
        float4 v0 = xr4[0], v1 = xr4[1];
        float xv[8] = {v0.x, v0.y, v0.z, v0.w, v1.x, v1.y, v1.z, v1.w};
        float sx = 0.f;
        #pragma unroll
        for (int j = 0; j < 8; j++) {
            s_x[r][j]   = xv[j];
            s_x25[r][j] = xv[j] + 0.25f;              // same rounding as before
            sx += xv[j];
        }
        s_p1c[r] = -0.5f * sx - 0.5f;
        s_key[r] = 0ull;
    }
    __syncthreads();

    const int lane = tid & 31;

    #pragma unroll 2
    for (int r = 0; r < 8; r++) {
        float x[8], x25[8];
        {
            const float4* p4 = reinterpret_cast<const float4*>(s_x[r]);
            float4 v0 = p4[0], v1 = p4[1];
            x[0]=v0.x; x[1]=v0.y; x[2]=v0.z; x[3]=v0.w;
            x[4]=v1.x; x[5]=v1.y; x[6]=v1.z; x[7]=v1.w;
            const float4* q4 = reinterpret_cast<const float4*>(s_x25[r]);
            float4 w0 = q4[0], w1 = q4[1];
            x25[0]=w0.x; x25[1]=w0.y; x25[2]=w0.z; x25[3]=w0.w;
            x25[4]=w1.x; x25[5]=w1.y; x25[6]=w1.z; x25[7]=w1.w;
        }
        const float p1c = s_p1c[r];

        // ---- p = 0: score = 2*(S - [parity]*2*mn) - |a|^2
        float sc0;
        {
            float t[8];
            #pragma unroll
            for (int j = 0; j < 8; j++) t[j] = x[j] * a[j];
            int px = ((__float_as_int(t[0]) ^ __float_as_int(t[1])) ^
                      (__float_as_int(t[2]) ^ __float_as_int(t[3]))) ^
                     ((__float_as_int(t[4]) ^ __float_as_int(t[5])) ^
                      (__float_as_int(t[6]) ^ __float_as_int(t[7])));
            float S = ((fabsf(t[0]) + fabsf(t[1])) + (fabsf(t[2]) + fabsf(t[3])))
                    + ((fabsf(t[4]) + fabsf(t[5])) + (fabsf(t[6]) + fabsf(t[7])));
            float mn = fminf(fminf(fminf(fabsf(t[0]), fabsf(t[1])),
                                   fminf(fabsf(t[2]), fabsf(t[3]))),
                             fminf(fminf(fabsf(t[4]), fabsf(t[5])),
                                   fminf(fabsf(t[6]), fabsf(t[7]))));
            float Sadj = fmaf(-2.f, mn, S);
            float Sp = (px < 0) ? Sadj : S;           // sign of xor = parity of negs
            sc0 = fmaf(2.f, Sp, -na);
        }
        // ---- p = 1: u_j = a_j*(x_j+0.25); score += p1c
        float sc1;
        {
            float t[8];
            #pragma unroll
            for (int j = 0; j < 8; j++) t[j] = x25[j] * a[j];
            int px = ((__float_as_int(t[0]) ^ __float_as_int(t[1])) ^
                      (__float_as_int(t[2]) ^ __float_as_int(t[3]))) ^
                     ((__float_as_int(t[4]) ^ __float_as_int(t[5])) ^
                      (__float_as_int(t[6]) ^ __float_as_int(t[7])));
            float S = ((fabsf(t[0]) + fabsf(t[1])) + (fabsf(t[2]) + fabsf(t[3])))
                    + ((fabsf(t[4]) + fabsf(t[5])) + (fabsf(t[6]) + fabsf(t[7])));
            float mn = fminf(fminf(fminf(fabsf(t[0]), fabsf(t[1])),
                                   fminf(fabsf(t[2]), fabsf(t[3]))),
                             fminf(fminf(fabsf(t[4]), fabsf(t[5])),
                                   fminf(fabsf(t[6]), fabsf(t[7]))));
            float Sadj = fmaf(-2.f, mn, S);
            float Sp = (px < 0) ? Sadj : S;
            sc1 = fmaf(2.f, Sp, -na) + p1c;           // same rounding order as before
        }

        // Merge parities (p=0 wins exact ties), then warp butterfly argmax.
        float best; int cid;
        if (sc1 > sc0) { best = sc1; cid = (A << 1) | 1; }
        else           { best = sc0; cid = (A << 1); }

        #pragma unroll
        for (int off = 16; off; off >>= 1) {
            float ob = __shfl_xor_sync(0xffffffffu, best, off);
            int   oc = __shfl_xor_sync(0xffffffffu, cid,  off);
            if (ob > best || (ob == best && oc < cid)) { best = ob; cid = oc; }
        }
        if (lane == 0) {
            // Order-preserving f32 -> u32, then key = (u << 9) | (511 - cid):
            // max key == max score, tie -> lowest cid (A-major, matches argmax).
            int sb = __float_as_int(best);
            unsigned u = (unsigned)sb ^ (unsigned)((sb >> 31) | (int)0x80000000);
            unsigned long long key = ((unsigned long long)u << 9)
                                   | (unsigned long long)(511 - cid);
            atomicMax(&s_key[r], key);
        }
    }
    __syncthreads();

    // Component j of the value vector <- bit SHUF[j] of the sign field.
    // SHUF = {0,4,1,5,2,6,3,7} -> BITS[j] = 1 << SHUF[j].
    constexpr unsigned BITS[8] = {1u<<0, 1u<<4, 1u<<1, 1u<<5, 1u<<2, 1u<<6, 1u<<3, 1u<<7};

    // ---- Winner post-processing: the thread owning the winning A recomputes
    //      the exact sign mask + argmin flip and writes vals/idx/pack slot.
    #pragma unroll 1
    for (int r = 0; r < 8; r++) {
        const int cid = 511 - (int)(s_key[r] & 511ull);
        const int Aw = cid >> 1, pw = cid & 1;
        if (tid == Aw) {
            unsigned mk = 0, mnbit = 0;
            float mnv = 1e30f;
            #pragma unroll
            for (int j = 0; j < 8; j++) {
                float xx = pw ? s_x25[r][j] : s_x[r][j];
                float t  = xx * a[j];
                unsigned sgn = (unsigned)(__float_as_int(t) >> 31);
                mk |= sgn & BITS[j];
                float at = fabsf(t);
                if (at < mnv) { mnv = at; mnbit = BITS[j]; }   // strict: first min
            }
            if (__popc(mk) & 1) mk ^= mnbit;
            const int bestc = (Aw << 8) | ((int)mk ^ pw);      // p=1 flips bit 0

            const int dm = r >> 2, dn = r & 3;
            const int row = (2 * ipair + dm) * 32 + 4 * jg + dn;

            const float4* gv = reinterpret_cast<const float4*>(grid + (size_t)bestc * 8);
            float4 v0 = gv[0], v1 = gv[1];
            float4* o4 = reinterpret_cast<float4*>(out + (size_t)row * 8);
            o4[0] = v0;                                        // vals
            o4[1] = v1;
            out[65536 + row] = (float)bestc;                   // idxs
            s_bestc[r] = bestc;
        }
    }
    __syncthreads();

    // ---- Block-local _pack_idxs (int32 / x64-disabled semantics: the reference's
    //      sign32 << 32 saturates to 0 in XLA; packed = int32 wrap of abs32).
    if (tid < 2) {
        const int jj = tid;                           // jj = 0,1
        const int j  = 2 * jg + jj;
        int q00 = s_bestc[      2 * jj    ];          // (dm=0, dn=2jj)   -> (2i,   2j)
        int q10 = s_bestc[4 +   2 * jj    ];          // (dm=1, dn=2jj)   -> (2i+1, 2j)
        int q01 = s_bestc[      2 * jj + 1];          // (dm=0, dn=2jj+1) -> (2i,   2j+1)
        int q11 = s_bestc[4 +   2 * jj + 1];          // (dm=1, dn=2jj+1) -> (2i+1, 2j+1)

        unsigned abs32 = (unsigned)(q00 >> 8)
                       | ((unsigned)(q10 >> 8) << 8)
                       | ((unsigned)(q01 >> 8) << 16)
                       | ((unsigned)(q11 >> 8) << 24);

        // L from (i, j): aa=i>>3, b=i&7, c=j>>2, d=j&3 -> L = aa<<7 | c<<5 | b<<2 | d
        const int i = ipair;
        const int L = ((i >> 3) << 7) | ((j >> 2) << 5) | ((i & 7) << 2) | (j & 3);
        out[73728 + L] = (float)(int)abs32;           // int32 wrap, then f32 cast
    }
}

extern "C" void kernel_launch(void* const* d_in, const int* in_sizes, int n_in,
                              void* d_out, int out_size)
{
    const float* X         = (const float*)d_in[0];   // 256*32*8 = 65536
    const float* grid      = (const float*)d_in[1];   // 65536*8
    const float* grid_norm = (const float*)d_in[2];   // 65536
    float* out = (float*)d_out;                       // [vals | idxs | packed] fp32

    e8p_fused_kernel<<<1024, 256>>>(X, grid, grid_norm, out);
}

// round 8
// speedup vs baseline: 1.4147x; 1.4147x over previous
#include <cuda_runtime.h>
#include <cstdint>

// 512 blocks. Block bk: ipair = bk>>2 (row-pair of 256x32 idx matrix),
// jg0 = 2*(bk&3). Block covers two tiles jg = jg0, jg0+1 (16 rows).
// Warp w handles slot w of both tiles: dm=w>>2, dn=w&3,
//   row[tt] = (2*ipair+dm)*32 + 4*(jg0+tt)+dn.
// All 4 idx entries of each packed word live inside one block -> local pack.

__global__ void __launch_bounds__(256, 4) e8p_fused_kernel(
    const float* __restrict__ X,
    const float* __restrict__ grid,
    const float* __restrict__ grid_norm,
    float* __restrict__ out)
{
    // Abs-code table: a[A] = grid[A<<8], stride 12 floats (48B) -> LDS.128 conflict-free.
    __shared__ __align__(16) float s_a[256][12];
    __shared__ float s_norm[256];
    __shared__ int s_bestc[16];

    const int tid = threadIdx.x;
    {
        const int A = tid;                            // exactly 256 threads
        const float4* g4 = reinterpret_cast<const float4*>(grid + ((size_t)A << 11));
        float4* d4 = reinterpret_cast<float4*>(s_a[A]);
        d4[0] = g4[0];
        d4[1] = g4[1];
        s_norm[A] = grid_norm[A << 8];
    }
    __syncthreads();

    const int warp = tid >> 5, lane = tid & 31;
    const int ipair = blockIdx.x >> 2;                // 0..127
    const int jg0   = (blockIdx.x & 3) * 2;           // 0,2,4,6
    const int dm = warp >> 2, dn = warp & 3;

    int   row[2];
    float x[2][8], p1c[2];
    #pragma unroll
    for (int tt = 0; tt < 2; tt++) {
        row[tt] = (2 * ipair + dm) * 32 + 4 * (jg0 + tt) + dn;
        const float4* xr4 = reinterpret_cast<const float4*>(X + (size_t)row[tt] * 8);
        float4 v0 = xr4[0], v1 = xr4[1];
        x[tt][0]=v0.x; x[tt][1]=v0.y; x[tt][2]=v0.z; x[tt][3]=v0.w;
        x[tt][4]=v1.x; x[tt][5]=v1.y; x[tt][6]=v1.z; x[tt][7]=v1.w;
        float sx = 0.f;
        #pragma unroll
        for (int j = 0; j < 8; j++) sx += x[tt][j];
        p1c[tt] = -0.5f * sx - 0.5f;
    }

    // Per-row, per-parity best chains (4 independent chains -> ILP).
    float best0[2] = {-1e30f, -1e30f}, best1[2] = {-1e30f, -1e30f};
    int   cA0[2]   = {0x7fffffff, 0x7fffffff}, cA1[2] = {0x7fffffff, 0x7fffffff};

    #pragma unroll
    for (int k = 0; k < 8; k++) {
        const int A = lane + (k << 5);
        float a[8];
        {
            const float4* p4 = reinterpret_cast<const float4*>(s_a[A]);
            float4 a0 = p4[0], a1 = p4[1];
            a[0]=a0.x; a[1]=a0.y; a[2]=a0.z; a[3]=a0.w;
            a[4]=a1.x; a[5]=a1.y; a[6]=a1.z; a[7]=a1.w;
        }
        const float na = s_norm[A];

        #pragma unroll
        for (int tt = 0; tt < 2; tt++) {
            float t[8], tp[8];
            #pragma unroll
            for (int j = 0; j < 8; j++) {
                t[j]  = x[tt][j] * a[j];
                tp[j] = fmaf(0.25f, a[j], t[j]);      // == (x+0.25)*a up to 1 ulp
            }
            // ---- p = 0: score = 2*(S - [parity]*2*mn) - |a|^2
            {
                int px = ((__float_as_int(t[0]) ^ __float_as_int(t[1])) ^
                          (__float_as_int(t[2]) ^ __float_as_int(t[3]))) ^
                         ((__float_as_int(t[4]) ^ __float_as_int(t[5])) ^
                          (__float_as_int(t[6]) ^ __float_as_int(t[7])));
                float S = ((fabsf(t[0]) + fabsf(t[1])) + (fabsf(t[2]) + fabsf(t[3])))
                        + ((fabsf(t[4]) + fabsf(t[5])) + (fabsf(t[6]) + fabsf(t[7])));
                float mn = fminf(fminf(fminf(fabsf(t[0]), fabsf(t[1])),
                                       fminf(fabsf(t[2]), fabsf(t[3]))),
                                 fminf(fminf(fabsf(t[4]), fabsf(t[5])),
                                       fminf(fabsf(t[6]), fabsf(t[7]))));
                float Sadj = fmaf(-2.f, mn, S);
                float Sp = (px < 0) ? Sadj : S;       // sign of xor = parity of negs
                float sc = fmaf(2.f, Sp, -na);
                if (sc > best0[tt]) { best0[tt] = sc; cA0[tt] = A; }  // first-wins
            }
            // ---- p = 1
            {
                int px = ((__float_as_int(tp[0]) ^ __float_as_int(tp[1])) ^
                          (__float_as_int(tp[2]) ^ __float_as_int(tp[3]))) ^
                         ((__float_as_int(tp[4]) ^ __float_as_int(tp[5])) ^
                          (__float_as_int(tp[6]) ^ __float_as_int(tp[7])));
                float S = ((fabsf(tp[0]) + fabsf(tp[1])) + (fabsf(tp[2]) + fabsf(tp[3])))
                        + ((fabsf(tp[4]) + fabsf(tp[5])) + (fabsf(tp[6]) + fabsf(tp[7])));
                float mn = fminf(fminf(fminf(fabsf(tp[0]), fabsf(tp[1])),
                                       fminf(fabsf(tp[2]), fabsf(tp[3]))),
                                 fminf(fminf(fabsf(tp[4]), fabsf(tp[5])),
                                       fminf(fabsf(tp[6]), fabsf(tp[7]))));
                float Sadj = fmaf(-2.f, mn, S);
                float Sp = (px < 0) ? Sadj : S;
                float sc = fmaf(2.f, Sp, -na) + p1c[tt];
                if (sc > best1[tt]) { best1[tt] = sc; cA1[tt] = A; }
            }
        }
    }

    // Component j of the value vector <- bit SHUF[j] of the sign field.
    // SHUF = {0,4,1,5,2,6,3,7} -> BITS[j] = 1 << SHUF[j].
    constexpr unsigned BITS[8] = {1u<<0, 1u<<4, 1u<<1, 1u<<5, 1u<<2, 1u<<6, 1u<<3, 1u<<7};

    #pragma unroll
    for (int tt = 0; tt < 2; tt++) {
        // Merge parity chains: p=0 wins exact same-A ties; lower A on cross ties.
        float best; int cid;
        if (best1[tt] > best0[tt] || (best1[tt] == best0[tt] && cA1[tt] < cA0[tt]))
             { best = best1[tt]; cid = (cA1[tt] << 1) | 1; }
        else { best = best0[tt]; cid = (cA0[tt] << 1); }

        // Warp argmax (butterfly, total order via cid tie-break).
        #pragma unroll
        for (int off = 16; off; off >>= 1) {
            float ob = __shfl_xor_sync(0xffffffffu, best, off);
            int   oc = __shfl_xor_sync(0xffffffffu, cid,  off);
            if (ob > best || (ob == best && oc < cid)) { best = ob; cid = oc; }
        }

        // Recompute full sign mask + argmin flip for the winning candidate.
        const int Aw = cid >> 1, pw = cid & 1;
        const float* av = s_a[Aw];
        unsigned mk = 0, mnbit = 0;
        float mnv = 1e30f;
        #pragma unroll
        for (int j = 0; j < 8; j++) {
            float t0 = x[tt][j] * av[j];
            float t  = pw ? fmaf(0.25f, av[j], t0) : t0;       // identical to scan
            unsigned sgn = (unsigned)(__float_as_int(t) >> 31);
            mk |= sgn & BITS[j];
            float at = fabsf(t);
            if (at < mnv) { mnv = at; mnbit = BITS[j]; }        // strict: first min
        }
        if (__popc(mk) & 1) mk ^= mnbit;
        const int bestc = (Aw << 8) | ((int)mk ^ pw);           // p=1 flips bit 0

        if (lane < 8) {
            out[(size_t)row[tt] * 8 + lane] = grid[(size_t)bestc * 8 + lane];  // vals
        }
        if (lane == 0) {
            out[65536 + row[tt]] = (float)bestc;                // idxs
            s_bestc[tt * 8 + warp] = bestc;
        }
    }
    __syncthreads();

    // ---- Block-local _pack_idxs (int32 / x64-disabled semantics: the reference's
    //      sign32 << 32 saturates to 0 in XLA; packed = int32 wrap of abs32).
    if (tid < 4) {
        const int ttp = tid >> 1, jj = tid & 1;
        const int base = ttp * 8;
        const int j = 2 * jg0 + tid;                  // column-pair index 0..15
        int q00 = s_bestc[base +     2 * jj    ];     // (dm=0, dn=2jj)   -> (2i,   2j)
        int q10 = s_bestc[base + 4 + 2 * jj    ];     // (dm=1, dn=2jj)   -> (2i+1, 2j)
        int q01 = s_bestc[base +     2 * jj + 1];     // (dm=0, dn=2jj+1) -> (2i,   2j+1)
        int q11 = s_bestc[base + 4 + 2 * jj + 1];     // (dm=1, dn=2jj+1) -> (2i+1, 2j+1)

        unsigned abs32 = (unsigned)(q00 >> 8)
                       | ((unsigned)(q10 >> 8) << 8)
                       | ((unsigned)(q01 >> 8) << 16)
                       | ((unsigned)(q11 >> 8) << 24);

        // L from (i, j): L = (i>>3)<<7 | (j>>2)<<5 | (i&7)<<2 | (j&3)
        const int i = ipair;
        const int L = ((i >> 3) << 7) | ((j >> 2) << 5) | ((i & 7) << 2) | (j & 3);
        out[73728 + L] = (float)(int)abs32;           // int32 wrap, then f32 cast
    }
}

extern "C" void kernel_launch(void* const* d_in, const int* in_sizes, int n_in,
                              void* d_out, int out_size)
{
    const float* X         = (const float*)d_in[0];   // 256*32*8 = 65536
    const float* grid      = (const float*)d_in[1];   // 65536*8
    const float* grid_norm = (const float*)d_in[2];   // 65536
    float* out = (float*)d_out;                       // [vals | idxs | packed] fp32

    e8p_fused_kernel<<<512, 256>>>(X, grid, grid_norm, out);
}